// round 3
// baseline (speedup 1.0000x reference)
#include <cuda_runtime.h>
#include <cuda_bf16.h>

// Problem constants (fixed by the reference)
#define N_NODES 50000
#define OUT_DIM 32

// Scratch (allocation-free): sums + counts for the mean scatter
__device__ float g_sums[N_NODES * OUT_DIM];
__device__ float g_cnt[N_NODES];

constexpr int TPB = 128;

// Per-thread shared activation rows. Odd strides -> conflict-free:
// addr bank = (t*stride + k) % 32 = (t + k) % 32 distinct across lanes.
constexpr int SA_STRIDE = 129;  // holds up to 128 floats/thread (in[64], then h2[128])
constexpr int SB_STRIDE = 65;   // holds up to 64 floats/thread (h1, then h3)
constexpr int W_FLOATS   = 8192;  // max weight tile (64x128 / 128x64) = 32KB
constexpr int BIAS_FLOATS = 128;
constexpr int SMEM_FLOATS = W_FLOATS + BIAS_FLOATS + TPB * SA_STRIDE + TPB * SB_STRIDE;
constexpr int SMEM_BYTES  = SMEM_FLOATS * 4;  // 132,608 B

__global__ void zero_kernel(int n_nodes) {
    int i = blockIdx.x * blockDim.x + threadIdx.x;
    if (i < n_nodes * OUT_DIM) g_sums[i] = 0.0f;
    if (i < n_nodes)           g_cnt[i]  = 0.0f;
}

__device__ __forceinline__ void copy_w4(float* dst, const float* __restrict__ src, int n4) {
    const float4* s = reinterpret_cast<const float4*>(src);
    float4*       d = reinterpret_cast<float4*>(dst);
    for (int i = threadIdx.x; i < n4; i += TPB) d[i] = s[i];
}

// One MLP layer: out[j] = relu(bias[j] + sum_k act[k] * W[k*J + j])
// act: per-thread shared row (conflict-free scalar LDS)
// W:   shared, all lanes read same address (broadcast), float4 -> LDS.128
template<int K, int J>
__device__ __forceinline__ void mlp_layer(const float* __restrict__ act,
                                          float* __restrict__ outp,
                                          const float* __restrict__ sW,
                                          const float* __restrict__ sBias) {
#pragma unroll 1
    for (int jt = 0; jt < J; jt += 8) {
        float a[8];
#pragma unroll
        for (int j = 0; j < 8; j++) a[j] = sBias[jt + j];
#pragma unroll 4
        for (int k = 0; k < K; k++) {
            float av = act[k];
            float4 w0 = *reinterpret_cast<const float4*>(sW + k * J + jt);
            float4 w1 = *reinterpret_cast<const float4*>(sW + k * J + jt + 4);
            a[0] = fmaf(av, w0.x, a[0]);
            a[1] = fmaf(av, w0.y, a[1]);
            a[2] = fmaf(av, w0.z, a[2]);
            a[3] = fmaf(av, w0.w, a[3]);
            a[4] = fmaf(av, w1.x, a[4]);
            a[5] = fmaf(av, w1.y, a[5]);
            a[6] = fmaf(av, w1.z, a[6]);
            a[7] = fmaf(av, w1.w, a[7]);
        }
#pragma unroll
        for (int j = 0; j < 8; j++) outp[jt + j] = fmaxf(a[j], 0.0f);
    }
}

__global__ __launch_bounds__(TPB)
void edge_mlp_kernel(const float* __restrict__ x,
                     const int* __restrict__ ei,   // [2, E] int32, dst = ei[E + e]
                     const float* __restrict__ ea,
                     const float* __restrict__ W1, const float* __restrict__ b1,
                     const float* __restrict__ W2, const float* __restrict__ b2,
                     const float* __restrict__ W3, const float* __restrict__ b3,
                     const float* __restrict__ W4, const float* __restrict__ b4,
                     int E, int n_nodes) {
    extern __shared__ float smem[];
    float* sW    = smem;
    float* sBias = sW + W_FLOATS;
    float* sA    = sBias + BIAS_FLOATS;
    float* sB    = sA + TPB * SA_STRIDE;

    const int t = threadIdx.x;
    const long long eid = (long long)blockIdx.x * TPB + t;
    const bool valid = (eid < (long long)E);

    float* myA = sA + t * SA_STRIDE;
    float* myB = sB + t * SB_STRIDE;

    // Stage W1 + b1 while gathering inputs
    copy_w4(sW, W1, 64 * 64 / 4);
    if (t < 64) sBias[t] = b1[t];

    int dst = 0;
    if (valid) {
        dst = ei[(size_t)E + eid];
        // defensive clamp: never index outside scratch even if dtype assumption is off
        dst = min(max(dst, 0), n_nodes - 1);
        const float4* xv = reinterpret_cast<const float4*>(x + (size_t)dst * 32);
        const float4* ev = reinterpret_cast<const float4*>(ea + (size_t)eid * 32);
#pragma unroll
        for (int i = 0; i < 8; i++) {
            float4 v = xv[i];
            myA[4 * i + 0] = v.x; myA[4 * i + 1] = v.y;
            myA[4 * i + 2] = v.z; myA[4 * i + 3] = v.w;
        }
#pragma unroll
        for (int i = 0; i < 8; i++) {
            float4 v = ev[i];
            myA[32 + 4 * i + 0] = v.x; myA[32 + 4 * i + 1] = v.y;
            myA[32 + 4 * i + 2] = v.z; myA[32 + 4 * i + 3] = v.w;
        }
    } else {
#pragma unroll
        for (int i = 0; i < 64; i++) myA[i] = 0.0f;
    }
    __syncthreads();

    // Layer 1: in[64] (A) -> h1[64] (B)
    mlp_layer<64, 64>(myA, myB, sW, sBias);
    __syncthreads();

    copy_w4(sW, W2, 64 * 128 / 4);
    if (t < 128) sBias[t] = b2[t];
    __syncthreads();

    // Layer 2: h1[64] (B) -> h2[128] (A)
    mlp_layer<64, 128>(myB, myA, sW, sBias);
    __syncthreads();

    copy_w4(sW, W3, 128 * 64 / 4);
    if (t < 64) sBias[t] = b3[t];
    __syncthreads();

    // Layer 3: h2[128] (A) -> h3[64] (B)
    mlp_layer<128, 64>(myA, myB, sW, sBias);
    __syncthreads();

    copy_w4(sW, W4, 64 * 32 / 4);
    if (t < 32) sBias[t] = b4[t];
    __syncthreads();

    // Layer 4 fused with mean-scatter (atomic accumulate)
    float* sums = &g_sums[(size_t)dst * OUT_DIM];
#pragma unroll 1
    for (int jt = 0; jt < OUT_DIM; jt += 8) {
        float a[8];
#pragma unroll
        for (int j = 0; j < 8; j++) a[j] = sBias[jt + j];
#pragma unroll 4
        for (int k = 0; k < 64; k++) {
            float av = myB[k];
            float4 w0 = *reinterpret_cast<const float4*>(sW + k * OUT_DIM + jt);
            float4 w1 = *reinterpret_cast<const float4*>(sW + k * OUT_DIM + jt + 4);
            a[0] = fmaf(av, w0.x, a[0]);
            a[1] = fmaf(av, w0.y, a[1]);
            a[2] = fmaf(av, w0.z, a[2]);
            a[3] = fmaf(av, w0.w, a[3]);
            a[4] = fmaf(av, w1.x, a[4]);
            a[5] = fmaf(av, w1.y, a[5]);
            a[6] = fmaf(av, w1.z, a[6]);
            a[7] = fmaf(av, w1.w, a[7]);
        }
        if (valid) {
#pragma unroll
            for (int j = 0; j < 8; j++) atomicAdd(&sums[jt + j], fmaxf(a[j], 0.0f));
        }
    }
    if (valid) atomicAdd(&g_cnt[dst], 1.0f);
}

__global__ void finalize_kernel(float* __restrict__ out, int n_nodes) {
    int i = blockIdx.x * blockDim.x + threadIdx.x;
    if (i < n_nodes * OUT_DIM) {
        float c = g_cnt[i / OUT_DIM];
        out[i] = g_sums[i] / fmaxf(c, 1.0f);
    }
}

extern "C" void kernel_launch(void* const* d_in, const int* in_sizes, int n_in,
                              void* d_out, int out_size) {
    const float* x  = (const float*)d_in[0];
    const int*   ei = (const int*)d_in[1];      // edge_index delivered as int32
    const float* ea = (const float*)d_in[2];
    const float* W1 = (const float*)d_in[3];  const float* b1 = (const float*)d_in[4];
    const float* W2 = (const float*)d_in[5];  const float* b2 = (const float*)d_in[6];
    const float* W3 = (const float*)d_in[7];  const float* b3 = (const float*)d_in[8];
    const float* W4 = (const float*)d_in[9];  const float* b4 = (const float*)d_in[10];

    const int E       = in_sizes[2] / 32;   // edge_attr is [E, 32]
    const int n_nodes = in_sizes[0] / 32;   // x is [N, 32]

    cudaFuncSetAttribute(edge_mlp_kernel,
                         cudaFuncAttributeMaxDynamicSharedMemorySize, SMEM_BYTES);

    const int zn = n_nodes * OUT_DIM;
    zero_kernel<<<(zn + 255) / 256, 256>>>(n_nodes);

    const int blocks = (E + TPB - 1) / TPB;
    edge_mlp_kernel<<<blocks, TPB, SMEM_BYTES>>>(x, ei, ea,
                                                 W1, b1, W2, b2, W3, b3, W4, b4,
                                                 E, n_nodes);

    finalize_kernel<<<(zn + 255) / 256, 256>>>((float*)d_out, n_nodes);
}

// round 6
// speedup vs baseline: 6.9643x; 6.9643x over previous
#include <cuda_runtime.h>
#include <cuda_bf16.h>
#include <cstdint>

#define N_NODES 50000
#define OUT_DIM 32

// ------------------------------------------------------------------ scratch
__device__ float g_sums[N_NODES * OUT_DIM];
__device__ float g_cnt[N_NODES];
// Transposed, padded, hi/lo-split bf16 weight image (99328 B = 6208 uint4)
__device__ uint4 g_wimg[6208];

constexpr int TPB      = 384;   // 12 warps
constexpr int ROWS_PW  = 16;    // edges per warp
constexpr int TILE     = (TPB / 32) * ROWS_PW;   // 192 edges per CTA tile

// Weight image offsets (bytes). Wt[j][k] row-major, stride = K*2+16.
constexpr int W1H = 0,     W1L = 9216;    // [64][64]  s=144
constexpr int W2H = 18432, W2L = 36864;   // [128][64] s=144
constexpr int W3H = 55296, W3L = 72704;   // [64][128] s=272
constexpr int W4H = 90112, W4L = 94720;   // [32][64]  s=144
constexpr int WIMG_BYTES = 99328;

// smem layout (bytes)
constexpr int SM_BIAS  = WIMG_BYTES;            // 288 floats
constexpr int SM_STAGE = SM_BIAS + 1152;        // per-warp 16 rows x 72 floats
constexpr int STAGE_PW = 16 * 72 * 4;           // 4608 B
constexpr int SMEM_BYTES = SM_STAGE + (TPB / 32) * STAGE_PW;  // 155776

// ------------------------------------------------------------- small kernels
__global__ void zero_kernel(int n_nodes) {
    int i = blockIdx.x * blockDim.x + threadIdx.x;
    if (i < n_nodes * OUT_DIM) g_sums[i] = 0.0f;
    if (i < n_nodes)           g_cnt[i]  = 0.0f;
}

__global__ void prep_weights(const float* __restrict__ W1, const float* __restrict__ W2,
                             const float* __restrict__ W3, const float* __restrict__ W4) {
    int idx = blockIdx.x * blockDim.x + threadIdx.x;
    if (idx >= 22528) return;
    float v; int hoff, loff;
    if (idx < 4096) {                     // W1 [64 in][64 out] -> Wt[64][64] s144
        int k = idx >> 6, j = idx & 63;
        v = W1[k * 64 + j];
        hoff = W1H + j * 144 + k * 2; loff = W1L + j * 144 + k * 2;
    } else if (idx < 12288) {             // W2 [64][128] -> Wt[128][64] s144
        int i2 = idx - 4096; int k = i2 >> 7, j = i2 & 127;
        v = W2[k * 128 + j];
        hoff = W2H + j * 144 + k * 2; loff = W2L + j * 144 + k * 2;
    } else if (idx < 20480) {             // W3 [128][64] -> Wt[64][128] s272
        int i2 = idx - 12288; int k = i2 >> 6, j = i2 & 63;
        v = W3[k * 64 + j];
        hoff = W3H + j * 272 + k * 2; loff = W3L + j * 272 + k * 2;
    } else {                              // W4 [64][32] -> Wt[32][64] s144
        int i2 = idx - 20480; int k = i2 >> 5, j = i2 & 31;
        v = W4[k * 32 + j];
        hoff = W4H + j * 144 + k * 2; loff = W4L + j * 144 + k * 2;
    }
    __nv_bfloat16 hi = __float2bfloat16(v);
    __nv_bfloat16 lo = __float2bfloat16(v - __bfloat162float(hi));
    char* img = (char*)g_wimg;
    *(__nv_bfloat16*)(img + hoff) = hi;
    *(__nv_bfloat16*)(img + loff) = lo;
}

__global__ void finalize_kernel(float* __restrict__ out, int n_nodes) {
    int i = blockIdx.x * blockDim.x + threadIdx.x;
    if (i < n_nodes * OUT_DIM) {
        float c = g_cnt[i / OUT_DIM];
        out[i] = g_sums[i] / fmaxf(c, 1.0f);
    }
}

// ---------------------------------------------------------------- primitives
__device__ __forceinline__ uint32_t smem_u32(const void* p) {
    uint32_t a;
    asm("{ .reg .u64 t; cvta.to.shared.u64 t, %1; cvt.u32.u64 %0, t; }" : "=r"(a) : "l"(p));
    return a;
}

__device__ __forceinline__ void ldsm4(uint32_t* r, uint32_t addr) {
    asm volatile("ldmatrix.sync.aligned.m8n8.x4.shared.b16 {%0,%1,%2,%3}, [%4];"
                 : "=r"(r[0]), "=r"(r[1]), "=r"(r[2]), "=r"(r[3]) : "r"(addr));
}

__device__ __forceinline__ void mma16816(float* d, const uint32_t* a,
                                         uint32_t b0, uint32_t b1) {
    asm volatile(
        "mma.sync.aligned.m16n8k16.row.col.f32.bf16.bf16.f32 "
        "{%0,%1,%2,%3}, {%4,%5,%6,%7}, {%8,%9}, {%0,%1,%2,%3};"
        : "+f"(d[0]), "+f"(d[1]), "+f"(d[2]), "+f"(d[3])
        : "r"(a[0]), "r"(a[1]), "r"(a[2]), "r"(a[3]), "r"(b0), "r"(b1));
}

__device__ __forceinline__ void split_pack(float a, float b, uint32_t& h, uint32_t& l) {
    __nv_bfloat162 hb = __floats2bfloat162_rn(a, b);
    float ra = a - __bfloat162float(hb.x);
    float rb = b - __bfloat162float(hb.y);
    __nv_bfloat162 lb = __floats2bfloat162_rn(ra, rb);
    h = *reinterpret_cast<uint32_t*>(&hb);
    l = *reinterpret_cast<uint32_t*>(&lb);
}

// GEMM for an n16 block pair (jb0, jb0+1): acc[0..3] = n8 block jb0, acc[4..7] = jb0+1.
// 3-term split: Ah*Bh + Al*Bh + Ah*Bl.
template<int K16, int STRIDE>
__device__ __forceinline__ void pair_gemm(float acc[8],
                                          const uint32_t (*Ah)[4], const uint32_t (*Al)[4],
                                          uint32_t bH, uint32_t bL, int jb0, int lane) {
#pragma unroll
    for (int i = 0; i < 8; i++) acc[i] = 0.0f;
    const uint32_t lo = (lane & 7) * STRIDE + (lane >> 3) * 16;
    const uint32_t r0 = jb0 * 8 * STRIDE, r1 = (jb0 + 1) * 8 * STRIDE;
#pragma unroll
    for (int c = 0; c < K16; c += 2) {
        uint32_t h0[4], h1[4], l0[4], l1[4];
        const uint32_t co = c * 32 + lo;
        ldsm4(h0, bH + r0 + co);
        ldsm4(h1, bH + r1 + co);
        ldsm4(l0, bL + r0 + co);
        ldsm4(l1, bL + r1 + co);
        mma16816(acc,     Ah[c],     h0[0], h0[1]);
        mma16816(acc + 4, Ah[c],     h1[0], h1[1]);
        mma16816(acc,     Al[c],     h0[0], h0[1]);
        mma16816(acc + 4, Al[c],     h1[0], h1[1]);
        mma16816(acc,     Ah[c],     l0[0], l0[1]);
        mma16816(acc + 4, Ah[c],     l1[0], l1[1]);
        mma16816(acc,     Ah[c + 1], h0[2], h0[3]);
        mma16816(acc + 4, Ah[c + 1], h1[2], h1[3]);
        mma16816(acc,     Al[c + 1], h0[2], h0[3]);
        mma16816(acc + 4, Al[c + 1], h1[2], h1[3]);
        mma16816(acc,     Ah[c + 1], l0[2], l0[3]);
        mma16816(acc + 4, Ah[c + 1], l1[2], l1[3]);
    }
}

// Fold an acc pair into the next layer's A fragment c (bias + ReLU + split).
__device__ __forceinline__ void epi_frag(const float acc[8], const float* bias2,
                                         int lane, uint32_t* nh, uint32_t* nl) {
    float2 b0 = *(const float2*)(bias2 + (lane & 3) * 2);
    float2 b1 = *(const float2*)(bias2 + 8 + (lane & 3) * 2);
    split_pack(fmaxf(acc[0] + b0.x, 0.f), fmaxf(acc[1] + b0.y, 0.f), nh[0], nl[0]);
    split_pack(fmaxf(acc[2] + b0.x, 0.f), fmaxf(acc[3] + b0.y, 0.f), nh[1], nl[1]);
    split_pack(fmaxf(acc[4] + b1.x, 0.f), fmaxf(acc[5] + b1.y, 0.f), nh[2], nl[2]);
    split_pack(fmaxf(acc[6] + b1.x, 0.f), fmaxf(acc[7] + b1.y, 0.f), nh[3], nl[3]);
}

// --------------------------------------------------------------- main kernel
__global__ __launch_bounds__(TPB, 1)
void gnn_mma_kernel(const float* __restrict__ x,
                    const int* __restrict__ ei,
                    const float* __restrict__ ea,
                    const float* __restrict__ b1, const float* __restrict__ b2,
                    const float* __restrict__ b3, const float* __restrict__ b4,
                    int E, int n_nodes, int ntiles) {
    extern __shared__ char smem[];
    const uint32_t sb = smem_u32(smem);
    const int t = threadIdx.x;
    const int wid = t >> 5;
    const int lane = t & 31;

    // stage weights + biases into smem
    {
        uint4* dst = (uint4*)smem;
        for (int i = t; i < 6208; i += TPB) dst[i] = g_wimg[i];
        float* sB = (float*)(smem + SM_BIAS);
        if (t < 64)  sB[t] = b1[t];
        if (t < 128) sB[64 + t] = b2[t];
        if (t < 64)  sB[192 + t] = b3[t];
        if (t < 32)  sB[256 + t] = b4[t];
    }
    __syncthreads();

    const float* sBias = (const float*)(smem + SM_BIAS);
    float* stg = (float*)(smem + SM_STAGE + wid * STAGE_PW);

    for (int tile = blockIdx.x; tile < ntiles; tile += gridDim.x) {
        const int ebase = tile * TILE + wid * ROWS_PW;

        // rows this lane owns in the MMA fragments
        const int rA = lane >> 2, rB = rA + 8;
        const int eA = ebase + rA, eB = ebase + rB;
        const bool validA = eA < E, validB = eB < E;
        int dstA = 0, dstB = 0;
        if (validA) dstA = min(max(ei[(size_t)E + eA], 0), n_nodes - 1);
        if (validB) dstB = min(max(ei[(size_t)E + eB], 0), n_nodes - 1);

        // degree counts
        if (lane < ROWS_PW) {
            int e = ebase + lane;
            if (e < E) {
                int d = min(max(ei[(size_t)E + e], 0), n_nodes - 1);
                atomicAdd(&g_cnt[d], 1.0f);
            }
        }

        // ---- coalesced gather into per-warp staging [16][72] ----
        __syncwarp();
#pragma unroll
        for (int p = 0; p < 8; p++) {
            int row = 2 * p + (lane >> 4);
            int q = lane & 15;
            int e = ebase + row;
            float4 v = make_float4(0.f, 0.f, 0.f, 0.f);
            if (e < E) {
                if (q < 8) {
                    int d = min(max(ei[(size_t)E + e], 0), n_nodes - 1);
                    v = ((const float4*)(x + (size_t)d * 32))[q];
                } else {
                    v = ((const float4*)(ea + (size_t)e * 32))[q - 8];
                }
            }
            *(float4*)(stg + row * 72 + q * 4) = v;
        }
        __syncwarp();

        // ---- build A1 fragments (K=64) with hi/lo split ----
        uint32_t A1h[4][4], A1l[4][4];
#pragma unroll
        for (int c = 0; c < 4; c++) {
            int colA = 16 * c + (lane & 3) * 2;
            float2 f0 = *(const float2*)(stg + rA * 72 + colA);
            float2 f1 = *(const float2*)(stg + rB * 72 + colA);
            float2 f2 = *(const float2*)(stg + rA * 72 + colA + 8);
            float2 f3 = *(const float2*)(stg + rB * 72 + colA + 8);
            split_pack(f0.x, f0.y, A1h[c][0], A1l[c][0]);
            split_pack(f1.x, f1.y, A1h[c][1], A1l[c][1]);
            split_pack(f2.x, f2.y, A1h[c][2], A1l[c][2]);
            split_pack(f3.x, f3.y, A1h[c][3], A1l[c][3]);
        }
        __syncwarp();

        float acc[8];

        // ---- L1: K=64 -> 64, then L2: 64 -> 128, L3: 128 -> 64, L4: 64 -> 32
        uint32_t A2h[4][4], A2l[4][4];
#pragma unroll
        for (int co = 0; co < 4; co++) {
            pair_gemm<4, 144>(acc, A1h, A1l, sb + W1H, sb + W1L, 2 * co, lane);
            epi_frag(acc, sBias + 0 + 16 * co, lane, A2h[co], A2l[co]);
        }

        uint32_t A3h[8][4], A3l[8][4];
#pragma unroll
        for (int co = 0; co < 8; co++) {
            pair_gemm<4, 144>(acc, A2h, A2l, sb + W2H, sb + W2L, 2 * co, lane);
            epi_frag(acc, sBias + 64 + 16 * co, lane, A3h[co], A3l[co]);
        }

        uint32_t A4h[4][4], A4l[4][4];
#pragma unroll
        for (int co = 0; co < 4; co++) {
            pair_gemm<8, 272>(acc, A3h, A3l, sb + W3H, sb + W3L, 2 * co, lane);
            epi_frag(acc, sBias + 192 + 16 * co, lane, A4h[co], A4l[co]);
        }

        // ---- L4 + vectorized atomic mean-scatter ----
#pragma unroll
        for (int co = 0; co < 2; co++) {
            pair_gemm<4, 144>(acc, A4h, A4l, sb + W4H, sb + W4L, 2 * co, lane);
            float2 b0 = *(const float2*)(sBias + 256 + 16 * co + (lane & 3) * 2);
            float2 b1 = *(const float2*)(sBias + 256 + 16 * co + 8 + (lane & 3) * 2);
            int col = 16 * co + (lane & 3) * 2;
            if (validA)
                atomicAdd((float2*)&g_sums[(size_t)dstA * 32 + col],
                          make_float2(fmaxf(acc[0] + b0.x, 0.f), fmaxf(acc[1] + b0.y, 0.f)));
            if (validB)
                atomicAdd((float2*)&g_sums[(size_t)dstB * 32 + col],
                          make_float2(fmaxf(acc[2] + b0.x, 0.f), fmaxf(acc[3] + b0.y, 0.f)));
            if (validA)
                atomicAdd((float2*)&g_sums[(size_t)dstA * 32 + col + 8],
                          make_float2(fmaxf(acc[4] + b1.x, 0.f), fmaxf(acc[5] + b1.y, 0.f)));
            if (validB)
                atomicAdd((float2*)&g_sums[(size_t)dstB * 32 + col + 8],
                          make_float2(fmaxf(acc[6] + b1.x, 0.f), fmaxf(acc[7] + b1.y, 0.f)));
        }
    }
}

// ------------------------------------------------------------------- launch
extern "C" void kernel_launch(void* const* d_in, const int* in_sizes, int n_in,
                              void* d_out, int out_size) {
    const float* x  = (const float*)d_in[0];
    const int*   ei = (const int*)d_in[1];
    const float* ea = (const float*)d_in[2];
    const float* W1 = (const float*)d_in[3];  const float* b1 = (const float*)d_in[4];
    const float* W2 = (const float*)d_in[5];  const float* b2 = (const float*)d_in[6];
    const float* W3 = (const float*)d_in[7];  const float* b3 = (const float*)d_in[8];
    const float* W4 = (const float*)d_in[9];  const float* b4 = (const float*)d_in[10];

    const int E       = in_sizes[2] / 32;
    const int n_nodes = in_sizes[0] / 32;
    const int ntiles  = (E + TILE - 1) / TILE;

    int dev = 0, sms = 148;
    cudaGetDevice(&dev);
    cudaDeviceGetAttribute(&sms, cudaDevAttrMultiProcessorCount, dev);
    cudaFuncSetAttribute(gnn_mma_kernel,
                         cudaFuncAttributeMaxDynamicSharedMemorySize, SMEM_BYTES);

    prep_weights<<<(22528 + 255) / 256, 256>>>(W1, W2, W3, W4);
    const int zn = n_nodes * OUT_DIM;
    zero_kernel<<<(zn + 255) / 256, 256>>>(n_nodes);

    const int grid = (sms < ntiles) ? sms : ntiles;
    gnn_mma_kernel<<<grid, TPB, SMEM_BYTES>>>(x, ei, ea, b1, b2, b3, b4,
                                              E, n_nodes, ntiles);

    finalize_kernel<<<(zn + 255) / 256, 256>>>((float*)d_out, n_nodes);
}

// round 7
// speedup vs baseline: 8.7720x; 1.2596x over previous
#include <cuda_runtime.h>
#include <cuda_fp16.h>
#include <cstdint>

#define N_NODES 50000
#define OUT_DIM 32

// ------------------------------------------------------------------ scratch
__device__ float g_sums[N_NODES * OUT_DIM];
__device__ float g_cnt[N_NODES];
// Transposed, padded fp16 weight image (hi plane only): 49664 B = 3104 uint4
__device__ uint4 g_wimg[3104];

constexpr int TPB      = 384;   // 12 warps
constexpr int ROWS_PW  = 16;    // edges per warp
constexpr int TILE     = (TPB / 32) * ROWS_PW;   // 192 edges per CTA tile

// Weight image offsets (bytes). Wt[j][k] row-major fp16, stride = K*2+16.
constexpr int W1H = 0;        // [64][64]   s=144  (9216 B)
constexpr int W2H = 9216;     // [128][64]  s=144  (18432 B)
constexpr int W3H = 27648;    // [64][128]  s=272  (17408 B)
constexpr int W4H = 45056;    // [32][64]   s=144  (4608 B)
constexpr int WIMG_BYTES = 49664;

// smem layout (bytes)
constexpr int SM_BIAS  = WIMG_BYTES;            // 288 floats
constexpr int SM_STAGE = SM_BIAS + 1152;        // per-warp 16 rows x 72 floats
constexpr int STAGE_PW = 16 * 72 * 4;           // 4608 B
constexpr int SMEM_BYTES = SM_STAGE + (TPB / 32) * STAGE_PW;  // 106112

// ------------------------------------------------------------- small kernels
__global__ void zero_kernel(int n_nodes) {
    int i = blockIdx.x * blockDim.x + threadIdx.x;
    if (i < n_nodes * OUT_DIM) g_sums[i] = 0.0f;
    if (i < n_nodes)           g_cnt[i]  = 0.0f;
}

__global__ void prep_weights(const float* __restrict__ W1, const float* __restrict__ W2,
                             const float* __restrict__ W3, const float* __restrict__ W4) {
    int idx = blockIdx.x * blockDim.x + threadIdx.x;
    if (idx >= 22528) return;
    float v; int hoff;
    if (idx < 4096) {                     // W1 [64 in][64 out] -> Wt[64][64] s144
        int k = idx >> 6, j = idx & 63;
        v = W1[k * 64 + j];
        hoff = W1H + j * 144 + k * 2;
    } else if (idx < 12288) {             // W2 [64][128] -> Wt[128][64] s144
        int i2 = idx - 4096; int k = i2 >> 7, j = i2 & 127;
        v = W2[k * 128 + j];
        hoff = W2H + j * 144 + k * 2;
    } else if (idx < 20480) {             // W3 [128][64] -> Wt[64][128] s272
        int i2 = idx - 12288; int k = i2 >> 6, j = i2 & 63;
        v = W3[k * 64 + j];
        hoff = W3H + j * 272 + k * 2;
    } else {                              // W4 [64][32] -> Wt[32][64] s144
        int i2 = idx - 20480; int k = i2 >> 5, j = i2 & 31;
        v = W4[k * 32 + j];
        hoff = W4H + j * 144 + k * 2;
    }
    char* img = (char*)g_wimg;
    *(__half*)(img + hoff) = __float2half(v);
}

__global__ void finalize_kernel(float* __restrict__ out, int n_nodes) {
    int i = blockIdx.x * blockDim.x + threadIdx.x;
    if (i < n_nodes * OUT_DIM) {
        float c = g_cnt[i / OUT_DIM];
        out[i] = g_sums[i] / fmaxf(c, 1.0f);
    }
}

// ---------------------------------------------------------------- primitives
__device__ __forceinline__ uint32_t smem_u32(const void* p) {
    uint32_t a;
    asm("{ .reg .u64 t; cvta.to.shared.u64 t, %1; cvt.u32.u64 %0, t; }" : "=r"(a) : "l"(p));
    return a;
}

__device__ __forceinline__ void ldsm4(uint32_t* r, uint32_t addr) {
    asm volatile("ldmatrix.sync.aligned.m8n8.x4.shared.b16 {%0,%1,%2,%3}, [%4];"
                 : "=r"(r[0]), "=r"(r[1]), "=r"(r[2]), "=r"(r[3]) : "r"(addr));
}

__device__ __forceinline__ void mma16816(float* d, const uint32_t* a,
                                         uint32_t b0, uint32_t b1) {
    asm volatile(
        "mma.sync.aligned.m16n8k16.row.col.f32.f16.f16.f32 "
        "{%0,%1,%2,%3}, {%4,%5,%6,%7}, {%8,%9}, {%0,%1,%2,%3};"
        : "+f"(d[0]), "+f"(d[1]), "+f"(d[2]), "+f"(d[3])
        : "r"(a[0]), "r"(a[1]), "r"(a[2]), "r"(a[3]), "r"(b0), "r"(b1));
}

// split float pair into fp16 hi + fp16 residual lo (packed half2 words)
__device__ __forceinline__ void split_pack(float a, float b, uint32_t& h, uint32_t& l) {
    __half2 hb = __floats2half2_rn(a, b);
    float2 hf = __half22float2(hb);
    __half2 lb = __floats2half2_rn(a - hf.x, b - hf.y);
    h = *reinterpret_cast<uint32_t*>(&hb);
    l = *reinterpret_cast<uint32_t*>(&lb);
}

__device__ __forceinline__ void red4(float* p, float a, float b, float c, float d) {
    asm volatile("red.global.add.v4.f32 [%0], {%1,%2,%3,%4};"
                 :: "l"(p), "f"(a), "f"(b), "f"(c), "f"(d) : "memory");
}

// GEMM for 4 consecutive n8 blocks (jb0..jb0+3): acc[4i..4i+3] = block jb0+i.
// 2-term split: Ah*Bh + Al*Bh. 4 independent accumulation chains.
template<int K16, int STRIDE>
__device__ __forceinline__ void quad_gemm(float acc[16],
                                          const uint32_t (*Ah)[4], const uint32_t (*Al)[4],
                                          uint32_t bH, int jb0, int lane) {
#pragma unroll
    for (int i = 0; i < 16; i++) acc[i] = 0.0f;
    const uint32_t base = bH + (uint32_t)jb0 * 8 * STRIDE +
                          (lane & 7) * STRIDE + (lane >> 3) * 16;
#pragma unroll
    for (int c = 0; c < K16; c += 2) {
        uint32_t h[4][4];
#pragma unroll
        for (int i = 0; i < 4; i++) ldsm4(h[i], base + i * 8 * STRIDE + c * 32);
#pragma unroll
        for (int i = 0; i < 4; i++) mma16816(acc + 4 * i, Ah[c], h[i][0], h[i][1]);
#pragma unroll
        for (int i = 0; i < 4; i++) mma16816(acc + 4 * i, Al[c], h[i][0], h[i][1]);
#pragma unroll
        for (int i = 0; i < 4; i++) mma16816(acc + 4 * i, Ah[c + 1], h[i][2], h[i][3]);
#pragma unroll
        for (int i = 0; i < 4; i++) mma16816(acc + 4 * i, Al[c + 1], h[i][2], h[i][3]);
    }
}

// Fold an acc pair (2 n8 blocks = one k16 A-fragment) into next layer's A frag.
__device__ __forceinline__ void epi_frag(const float acc[8], const float* bias2,
                                         int lane, uint32_t* nh, uint32_t* nl) {
    float2 b0 = *(const float2*)(bias2 + (lane & 3) * 2);
    float2 b1 = *(const float2*)(bias2 + 8 + (lane & 3) * 2);
    split_pack(fmaxf(acc[0] + b0.x, 0.f), fmaxf(acc[1] + b0.y, 0.f), nh[0], nl[0]);
    split_pack(fmaxf(acc[2] + b0.x, 0.f), fmaxf(acc[3] + b0.y, 0.f), nh[1], nl[1]);
    split_pack(fmaxf(acc[4] + b1.x, 0.f), fmaxf(acc[5] + b1.y, 0.f), nh[2], nl[2]);
    split_pack(fmaxf(acc[6] + b1.x, 0.f), fmaxf(acc[7] + b1.y, 0.f), nh[3], nl[3]);
}

// --------------------------------------------------------------- main kernel
__global__ __launch_bounds__(TPB, 1)
void gnn_mma_kernel(const float* __restrict__ x,
                    const int* __restrict__ ei,
                    const float* __restrict__ ea,
                    const float* __restrict__ b1, const float* __restrict__ b2,
                    const float* __restrict__ b3, const float* __restrict__ b4,
                    int E, int n_nodes, int ntiles) {
    extern __shared__ char smem[];
    const uint32_t sb = smem_u32(smem);
    const int t = threadIdx.x;
    const int wid = t >> 5;
    const int lane = t & 31;

    // stage weights + biases into smem
    {
        uint4* dst = (uint4*)smem;
        for (int i = t; i < 3104; i += TPB) dst[i] = g_wimg[i];
        float* sB = (float*)(smem + SM_BIAS);
        if (t < 64)  sB[t] = b1[t];
        if (t < 128) sB[64 + t] = b2[t];
        if (t < 64)  sB[192 + t] = b3[t];
        if (t < 32)  sB[256 + t] = b4[t];
    }
    __syncthreads();

    const float* sBias = (const float*)(smem + SM_BIAS);
    float* stg = (float*)(smem + SM_STAGE + wid * STAGE_PW);

    for (int tile = blockIdx.x; tile < ntiles; tile += gridDim.x) {
        const int ebase = tile * TILE + wid * ROWS_PW;

        const int rA = lane >> 2, rB = rA + 8;
        const int eA = ebase + rA, eB = ebase + rB;
        const bool validA = eA < E, validB = eB < E;
        int dstA = 0, dstB = 0;
        if (validA) dstA = min(max(ei[(size_t)E + eA], 0), n_nodes - 1);
        if (validB) dstB = min(max(ei[(size_t)E + eB], 0), n_nodes - 1);

        // degree counts
        if (lane < ROWS_PW) {
            int e = ebase + lane;
            if (e < E) {
                int d = min(max(ei[(size_t)E + e], 0), n_nodes - 1);
                atomicAdd(&g_cnt[d], 1.0f);
            }
        }

        // ---- coalesced gather into per-warp staging [16][72] ----
        __syncwarp();
#pragma unroll
        for (int p = 0; p < 8; p++) {
            int row = 2 * p + (lane >> 4);
            int q = lane & 15;
            int e = ebase + row;
            float4 v = make_float4(0.f, 0.f, 0.f, 0.f);
            if (e < E) {
                if (q < 8) {
                    int d = min(max(ei[(size_t)E + e], 0), n_nodes - 1);
                    v = ((const float4*)(x + (size_t)d * 32))[q];
                } else {
                    v = ((const float4*)(ea + (size_t)e * 32))[q - 8];
                }
            }
            *(float4*)(stg + row * 72 + q * 4) = v;
        }
        __syncwarp();

        // ---- build A1 fragments (K=64) with fp16 hi/lo split ----
        uint32_t A1h[4][4], A1l[4][4];
#pragma unroll
        for (int c = 0; c < 4; c++) {
            int colA = 16 * c + (lane & 3) * 2;
            float2 f0 = *(const float2*)(stg + rA * 72 + colA);
            float2 f1 = *(const float2*)(stg + rB * 72 + colA);
            float2 f2 = *(const float2*)(stg + rA * 72 + colA + 8);
            float2 f3 = *(const float2*)(stg + rB * 72 + colA + 8);
            split_pack(f0.x, f0.y, A1h[c][0], A1l[c][0]);
            split_pack(f1.x, f1.y, A1h[c][1], A1l[c][1]);
            split_pack(f2.x, f2.y, A1h[c][2], A1l[c][2]);
            split_pack(f3.x, f3.y, A1h[c][3], A1l[c][3]);
        }
        __syncwarp();

        float acc[16];

        // ---- L1: 64 -> 64 (8 blocks = 2 quads) ----
        uint32_t A2h[4][4], A2l[4][4];
#pragma unroll
        for (int q = 0; q < 2; q++) {
            quad_gemm<4, 144>(acc, A1h, A1l, sb + W1H, 4 * q, lane);
            epi_frag(acc,     sBias + 32 * q,      lane, A2h[2 * q],     A2l[2 * q]);
            epi_frag(acc + 8, sBias + 32 * q + 16, lane, A2h[2 * q + 1], A2l[2 * q + 1]);
        }

        // ---- L2: 64 -> 128 (16 blocks = 4 quads) ----
        uint32_t A3h[8][4], A3l[8][4];
#pragma unroll
        for (int q = 0; q < 4; q++) {
            quad_gemm<4, 144>(acc, A2h, A2l, sb + W2H, 4 * q, lane);
            epi_frag(acc,     sBias + 64 + 32 * q,      lane, A3h[2 * q],     A3l[2 * q]);
            epi_frag(acc + 8, sBias + 64 + 32 * q + 16, lane, A3h[2 * q + 1], A3l[2 * q + 1]);
        }

        // ---- L3: 128 -> 64 (2 quads, K16=8) ----
        uint32_t A4h[4][4], A4l[4][4];
#pragma unroll
        for (int q = 0; q < 2; q++) {
            quad_gemm<8, 272>(acc, A3h, A3l, sb + W3H, 4 * q, lane);
            epi_frag(acc,     sBias + 192 + 32 * q,      lane, A4h[2 * q],     A4l[2 * q]);
            epi_frag(acc + 8, sBias + 192 + 32 * q + 16, lane, A4h[2 * q + 1], A4l[2 * q + 1]);
        }

        // ---- L4: 64 -> 32 (1 quad) + float4 red scatter ----
        quad_gemm<4, 144>(acc, A4h, A4l, sb + W4H, 0, lane);
        {
            const float* b4s = sBias + 256;
#pragma unroll
            for (int b = 0; b < 4; b++) {
                float2 bb = *(const float2*)(b4s + 8 * b + (lane & 3) * 2);
                float a0 = fmaxf(acc[4 * b + 0] + bb.x, 0.f);
                float a1 = fmaxf(acc[4 * b + 1] + bb.y, 0.f);
                float a2 = fmaxf(acc[4 * b + 2] + bb.x, 0.f);
                float a3 = fmaxf(acc[4 * b + 3] + bb.y, 0.f);
                // pair lanes (q, q^1): even q lane owns cols 8b+2q..+3 after merge
                float p0 = __shfl_xor_sync(0xFFFFFFFFu, a0, 1);
                float p1 = __shfl_xor_sync(0xFFFFFFFFu, a1, 1);
                float p2 = __shfl_xor_sync(0xFFFFFFFFu, a2, 1);
                float p3 = __shfl_xor_sync(0xFFFFFFFFu, a3, 1);
                if ((lane & 1) == 0) {
                    int col = 8 * b + (lane & 3) * 2;
                    if (validA) red4(&g_sums[(size_t)dstA * 32 + col], a0, a1, p0, p1);
                    if (validB) red4(&g_sums[(size_t)dstB * 32 + col], a2, a3, p2, p3);
                }
            }
        }
    }
}

// ------------------------------------------------------------------- launch
extern "C" void kernel_launch(void* const* d_in, const int* in_sizes, int n_in,
                              void* d_out, int out_size) {
    const float* x  = (const float*)d_in[0];
    const int*   ei = (const int*)d_in[1];
    const float* ea = (const float*)d_in[2];
    const float* W1 = (const float*)d_in[3];  const float* b1 = (const float*)d_in[4];
    const float* W2 = (const float*)d_in[5];  const float* b2 = (const float*)d_in[6];
    const float* W3 = (const float*)d_in[7];  const float* b3 = (const float*)d_in[8];
    const float* W4 = (const float*)d_in[9];  const float* b4 = (const float*)d_in[10];

    const int E       = in_sizes[2] / 32;
    const int n_nodes = in_sizes[0] / 32;
    const int ntiles  = (E + TILE - 1) / TILE;

    int dev = 0, sms = 148;
    cudaGetDevice(&dev);
    cudaDeviceGetAttribute(&sms, cudaDevAttrMultiProcessorCount, dev);
    cudaFuncSetAttribute(gnn_mma_kernel,
                         cudaFuncAttributeMaxDynamicSharedMemorySize, SMEM_BYTES);

    prep_weights<<<(22528 + 255) / 256, 256>>>(W1, W2, W3, W4);
    const int zn = n_nodes * OUT_DIM;
    zero_kernel<<<(zn + 255) / 256, 256>>>(n_nodes);

    const int grid = (sms < ntiles) ? sms : ntiles;
    gnn_mma_kernel<<<grid, TPB, SMEM_BYTES>>>(x, ei, ea, b1, b2, b3, b4,
                                              E, n_nodes, ntiles);

    finalize_kernel<<<(zn + 255) / 256, 256>>>((float*)d_out, n_nodes);
}

// round 8
// speedup vs baseline: 13.6565x; 1.5568x over previous
#include <cuda_runtime.h>
#include <cuda_fp16.h>
#include <cstdint>

#define N_NODES 50000
#define OUT_DIM 32

// ------------------------------------------------------------------ scratch
__device__ float g_sums[N_NODES * OUT_DIM];
__device__ float g_cnt[N_NODES];
// Transposed, padded fp16 weight image: 49664 B = 3104 uint4
__device__ uint4 g_wimg[3104];

constexpr int TPB      = 512;   // 16 warps
constexpr int ROWS_PW  = 16;    // edges per warp
constexpr int TILE     = (TPB / 32) * ROWS_PW;   // 256 edges per CTA tile

// Weight image offsets (bytes). Wt[j][k] row-major fp16, stride = K*2+16.
constexpr int W1H = 0;        // [64][64]   s=144  (9216 B)
constexpr int W2H = 9216;     // [128][64]  s=144  (18432 B)
constexpr int W3H = 27648;    // [64][128]  s=272  (17408 B)
constexpr int W4H = 45056;    // [32][64]   s=144  (4608 B)
constexpr int WIMG_BYTES = 49664;

// smem layout (bytes)
constexpr int SM_BIAS  = WIMG_BYTES;            // 288 floats
constexpr int SM_STAGE = SM_BIAS + 1152;        // per-warp 16 rows x 72 floats
constexpr int STAGE_PW = 16 * 72 * 4;           // 4608 B
constexpr int SMEM_BYTES = SM_STAGE + (TPB / 32) * STAGE_PW;  // 124544

// ------------------------------------------------------------- small kernels
__global__ void zero_kernel(int n_nodes) {
    int i = blockIdx.x * blockDim.x + threadIdx.x;
    if (i < n_nodes * OUT_DIM) g_sums[i] = 0.0f;
    if (i < n_nodes)           g_cnt[i]  = 0.0f;
}

__global__ void prep_weights(const float* __restrict__ W1, const float* __restrict__ W2,
                             const float* __restrict__ W3, const float* __restrict__ W4) {
    int idx = blockIdx.x * blockDim.x + threadIdx.x;
    if (idx >= 22528) return;
    float v; int hoff;
    if (idx < 4096) {                     // W1 [64 in][64 out] -> Wt[64][64] s144
        int k = idx >> 6, j = idx & 63;
        v = W1[k * 64 + j];
        hoff = W1H + j * 144 + k * 2;
    } else if (idx < 12288) {             // W2 [64][128] -> Wt[128][64] s144
        int i2 = idx - 4096; int k = i2 >> 7, j = i2 & 127;
        v = W2[k * 128 + j];
        hoff = W2H + j * 144 + k * 2;
    } else if (idx < 20480) {             // W3 [128][64] -> Wt[64][128] s272
        int i2 = idx - 12288; int k = i2 >> 6, j = i2 & 63;
        v = W3[k * 64 + j];
        hoff = W3H + j * 272 + k * 2;
    } else {                              // W4 [64][32] -> Wt[32][64] s144
        int i2 = idx - 20480; int k = i2 >> 5, j = i2 & 31;
        v = W4[k * 32 + j];
        hoff = W4H + j * 144 + k * 2;
    }
    char* img = (char*)g_wimg;
    *(__half*)(img + hoff) = __float2half(v);
}

__global__ void finalize_kernel(float* __restrict__ out, int n_nodes) {
    int i = blockIdx.x * blockDim.x + threadIdx.x;
    if (i < n_nodes * OUT_DIM) {
        float c = g_cnt[i / OUT_DIM];
        out[i] = g_sums[i] / fmaxf(c, 1.0f);
    }
}

// ---------------------------------------------------------------- primitives
__device__ __forceinline__ uint32_t smem_u32(const void* p) {
    uint32_t a;
    asm("{ .reg .u64 t; cvta.to.shared.u64 t, %1; cvt.u32.u64 %0, t; }" : "=r"(a) : "l"(p));
    return a;
}

__device__ __forceinline__ void ldsm4(uint32_t* r, uint32_t addr) {
    asm volatile("ldmatrix.sync.aligned.m8n8.x4.shared.b16 {%0,%1,%2,%3}, [%4];"
                 : "=r"(r[0]), "=r"(r[1]), "=r"(r[2]), "=r"(r[3]) : "r"(addr));
}

__device__ __forceinline__ void mma16816(float* d, const uint32_t* a,
                                         uint32_t b0, uint32_t b1) {
    asm volatile(
        "mma.sync.aligned.m16n8k16.row.col.f32.f16.f16.f32 "
        "{%0,%1,%2,%3}, {%4,%5,%6,%7}, {%8,%9}, {%0,%1,%2,%3};"
        : "+f"(d[0]), "+f"(d[1]), "+f"(d[2]), "+f"(d[3])
        : "r"(a[0]), "r"(a[1]), "r"(a[2]), "r"(a[3]), "r"(b0), "r"(b1));
}

__device__ __forceinline__ uint32_t pack_h2(float a, float b) {
    __half2 hb = __floats2half2_rn(a, b);
    return *reinterpret_cast<uint32_t*>(&hb);
}

__device__ __forceinline__ void red4(float* p, float a, float b, float c, float d) {
    asm volatile("red.global.add.v4.f32 [%0], {%1,%2,%3,%4};"
                 :: "l"(p), "f"(a), "f"(b), "f"(c), "f"(d) : "memory");
}

// GEMM for 4 consecutive n8 blocks (jb0..jb0+3): acc[4i..4i+3] = block jb0+i.
// Pure fp16 (1-term), f32 accumulate. 4 independent accumulation chains.
template<int K16, int STRIDE>
__device__ __forceinline__ void quad_gemm(float acc[16],
                                          const uint32_t (*Ah)[4],
                                          uint32_t bH, int jb0, int lane) {
#pragma unroll
    for (int i = 0; i < 16; i++) acc[i] = 0.0f;
    const uint32_t base = bH + (uint32_t)jb0 * 8 * STRIDE +
                          (lane & 7) * STRIDE + (lane >> 3) * 16;
#pragma unroll
    for (int c = 0; c < K16; c += 2) {
        uint32_t h[4][4];
#pragma unroll
        for (int i = 0; i < 4; i++) ldsm4(h[i], base + i * 8 * STRIDE + c * 32);
#pragma unroll
        for (int i = 0; i < 4; i++) mma16816(acc + 4 * i, Ah[c], h[i][0], h[i][1]);
#pragma unroll
        for (int i = 0; i < 4; i++) mma16816(acc + 4 * i, Ah[c + 1], h[i][2], h[i][3]);
    }
}

// Fold an acc pair (2 n8 blocks = one k16 A-fragment) into next layer's A frag.
__device__ __forceinline__ void epi_frag(const float acc[8], const float* bias2,
                                         int lane, uint32_t* nh) {
    float2 b0 = *(const float2*)(bias2 + (lane & 3) * 2);
    float2 b1 = *(const float2*)(bias2 + 8 + (lane & 3) * 2);
    nh[0] = pack_h2(fmaxf(acc[0] + b0.x, 0.f), fmaxf(acc[1] + b0.y, 0.f));
    nh[1] = pack_h2(fmaxf(acc[2] + b0.x, 0.f), fmaxf(acc[3] + b0.y, 0.f));
    nh[2] = pack_h2(fmaxf(acc[4] + b1.x, 0.f), fmaxf(acc[5] + b1.y, 0.f));
    nh[3] = pack_h2(fmaxf(acc[6] + b1.x, 0.f), fmaxf(acc[7] + b1.y, 0.f));
}

// --------------------------------------------------------------- main kernel
__global__ __launch_bounds__(TPB, 1)
void gnn_mma_kernel(const float* __restrict__ x,
                    const int* __restrict__ ei,
                    const float* __restrict__ ea,
                    const float* __restrict__ b1, const float* __restrict__ b2,
                    const float* __restrict__ b3, const float* __restrict__ b4,
                    int E, int n_nodes, int ntiles) {
    extern __shared__ char smem[];
    const uint32_t sb = smem_u32(smem);
    const int t = threadIdx.x;
    const int wid = t >> 5;
    const int lane = t & 31;

    // stage weights + biases into smem
    {
        uint4* dst = (uint4*)smem;
        for (int i = t; i < 3104; i += TPB) dst[i] = g_wimg[i];
        float* sB = (float*)(smem + SM_BIAS);
        if (t < 64)  sB[t] = b1[t];
        if (t < 128) sB[64 + t] = b2[t];
        if (t < 64)  sB[192 + t] = b3[t];
        if (t < 32)  sB[256 + t] = b4[t];
    }
    __syncthreads();

    const float* sBias = (const float*)(smem + SM_BIAS);
    float* stg = (float*)(smem + SM_STAGE + wid * STAGE_PW);

    for (int tile = blockIdx.x; tile < ntiles; tile += gridDim.x) {
        const int ebase = tile * TILE + wid * ROWS_PW;

        const int rA = lane >> 2, rB = rA + 8;
        const int eA = ebase + rA, eB = ebase + rB;
        const bool validA = eA < E, validB = eB < E;
        int dstA = 0, dstB = 0;
        if (validA) dstA = min(max(ei[(size_t)E + eA], 0), n_nodes - 1);
        if (validB) dstB = min(max(ei[(size_t)E + eB], 0), n_nodes - 1);

        // degree counts
        if (lane < ROWS_PW) {
            int e = ebase + lane;
            if (e < E) {
                int d = min(max(ei[(size_t)E + e], 0), n_nodes - 1);
                atomicAdd(&g_cnt[d], 1.0f);
            }
        }

        // ---- coalesced gather into per-warp staging [16][72] ----
        __syncwarp();
#pragma unroll
        for (int p = 0; p < 8; p++) {
            int row = 2 * p + (lane >> 4);
            int q = lane & 15;
            int e = ebase + row;
            float4 v = make_float4(0.f, 0.f, 0.f, 0.f);
            if (e < E) {
                if (q < 8) {
                    int d = min(max(ei[(size_t)E + e], 0), n_nodes - 1);
                    v = ((const float4*)(x + (size_t)d * 32))[q];
                } else {
                    v = ((const float4*)(ea + (size_t)e * 32))[q - 8];
                }
            }
            *(float4*)(stg + row * 72 + q * 4) = v;
        }
        __syncwarp();

        // ---- build A1 fragments (K=64), fp16 ----
        uint32_t A1h[4][4];
#pragma unroll
        for (int c = 0; c < 4; c++) {
            int colA = 16 * c + (lane & 3) * 2;
            float2 f0 = *(const float2*)(stg + rA * 72 + colA);
            float2 f1 = *(const float2*)(stg + rB * 72 + colA);
            float2 f2 = *(const float2*)(stg + rA * 72 + colA + 8);
            float2 f3 = *(const float2*)(stg + rB * 72 + colA + 8);
            A1h[c][0] = pack_h2(f0.x, f0.y);
            A1h[c][1] = pack_h2(f1.x, f1.y);
            A1h[c][2] = pack_h2(f2.x, f2.y);
            A1h[c][3] = pack_h2(f3.x, f3.y);
        }
        __syncwarp();

        float acc[16];

        // ---- L1: 64 -> 64 (2 quads) ----
        uint32_t A2h[4][4];
#pragma unroll
        for (int q = 0; q < 2; q++) {
            quad_gemm<4, 144>(acc, A1h, sb + W1H, 4 * q, lane);
            epi_frag(acc,     sBias + 32 * q,      lane, A2h[2 * q]);
            epi_frag(acc + 8, sBias + 32 * q + 16, lane, A2h[2 * q + 1]);
        }

        // ---- L2: 64 -> 128 (4 quads) ----
        uint32_t A3h[8][4];
#pragma unroll
        for (int q = 0; q < 4; q++) {
            quad_gemm<4, 144>(acc, A2h, sb + W2H, 4 * q, lane);
            epi_frag(acc,     sBias + 64 + 32 * q,      lane, A3h[2 * q]);
            epi_frag(acc + 8, sBias + 64 + 32 * q + 16, lane, A3h[2 * q + 1]);
        }

        // ---- L3: 128 -> 64 (2 quads, K16=8) ----
        uint32_t A4h[4][4];
#pragma unroll
        for (int q = 0; q < 2; q++) {
            quad_gemm<8, 272>(acc, A3h, sb + W3H, 4 * q, lane);
            epi_frag(acc,     sBias + 192 + 32 * q,      lane, A4h[2 * q]);
            epi_frag(acc + 8, sBias + 192 + 32 * q + 16, lane, A4h[2 * q + 1]);
        }

        // ---- L4: 64 -> 32 (1 quad) + float4 red scatter ----
        quad_gemm<4, 144>(acc, A4h, sb + W4H, 0, lane);
        {
            const float* b4s = sBias + 256;
#pragma unroll
            for (int b = 0; b < 4; b++) {
                float2 bb = *(const float2*)(b4s + 8 * b + (lane & 3) * 2);
                float a0 = fmaxf(acc[4 * b + 0] + bb.x, 0.f);
                float a1 = fmaxf(acc[4 * b + 1] + bb.y, 0.f);
                float a2 = fmaxf(acc[4 * b + 2] + bb.x, 0.f);
                float a3 = fmaxf(acc[4 * b + 3] + bb.y, 0.f);
                // pair lanes (q, q^1): even lane emits a 16B red covering both
                float p0 = __shfl_xor_sync(0xFFFFFFFFu, a0, 1);
                float p1 = __shfl_xor_sync(0xFFFFFFFFu, a1, 1);
                float p2 = __shfl_xor_sync(0xFFFFFFFFu, a2, 1);
                float p3 = __shfl_xor_sync(0xFFFFFFFFu, a3, 1);
                if ((lane & 1) == 0) {
                    int col = 8 * b + (lane & 3) * 2;
                    if (validA) red4(&g_sums[(size_t)dstA * 32 + col], a0, a1, p0, p1);
                    if (validB) red4(&g_sums[(size_t)dstB * 32 + col], a2, a3, p2, p3);
                }
            }
        }
    }
}

// ------------------------------------------------------------------- launch
extern "C" void kernel_launch(void* const* d_in, const int* in_sizes, int n_in,
                              void* d_out, int out_size) {
    const float* x  = (const float*)d_in[0];
    const int*   ei = (const int*)d_in[1];
    const float* ea = (const float*)d_in[2];
    const float* W1 = (const float*)d_in[3];  const float* b1 = (const float*)d_in[4];
    const float* W2 = (const float*)d_in[5];  const float* b2 = (const float*)d_in[6];
    const float* W3 = (const float*)d_in[7];  const float* b3 = (const float*)d_in[8];
    const float* W4 = (const float*)d_in[9];  const float* b4 = (const float*)d_in[10];

    const int E       = in_sizes[2] / 32;
    const int n_nodes = in_sizes[0] / 32;
    const int ntiles  = (E + TILE - 1) / TILE;

    int dev = 0, sms = 148;
    cudaGetDevice(&dev);
    cudaDeviceGetAttribute(&sms, cudaDevAttrMultiProcessorCount, dev);
    cudaFuncSetAttribute(gnn_mma_kernel,
                         cudaFuncAttributeMaxDynamicSharedMemorySize, SMEM_BYTES);

    prep_weights<<<(22528 + 255) / 256, 256>>>(W1, W2, W3, W4);
    const int zn = n_nodes * OUT_DIM;
    zero_kernel<<<(zn + 255) / 256, 256>>>(n_nodes);

    const int grid = (sms < ntiles) ? sms : ntiles;
    gnn_mma_kernel<<<grid, TPB, SMEM_BYTES>>>(x, ei, ea, b1, b2, b3, b4,
                                              E, n_nodes, ntiles);

    finalize_kernel<<<(zn + 255) / 256, 256>>>((float*)d_out, n_nodes);
}